// round 9
// baseline (speedup 1.0000x reference)
#include <cuda_runtime.h>
#include <math.h>
#include <stdint.h>

#define EN 300000
#define NN 50000
#define GN 1024
#define H  256
#define NCONV 4
#define PA 136      // A smem row stride: 136 mod 32 == 8 -> conflict-free frag loads
#define PB 264      // B smem row stride (256-wide tiles)
#define PB1 136     // B smem row stride (128-wide tiles)

// ---------------- scratch (device globals) ---------------------------------
static __device__ float g_bond[(size_t)EN * H];   // bond_attr [E,H] (edge order)
static __device__ float g_h[NN * H];
static __device__ float g_aggr[NN * H];
static __device__ float g_tmp[NN * H];
static __device__ float g_temb[GN];
static __device__ float g_invstd[GN];
static __device__ float g_einv[EN];
// sort machinery
static __device__ int g_cnt[NN];      // zero-init; scan re-zeroes each call
static __device__ int g_rp[NN + 1];
static __device__ int g_woff[NN];
static __device__ int g_srcp[EN];
static __device__ int g_eid[EN];

// ---------------- helpers ---------------------------------------------------
__device__ __forceinline__ float totf(float x) {
    uint32_t u; asm("cvt.rna.tf32.f32 %0, %1;" : "=r"(u) : "f"(x));
    return __uint_as_float(u);
}

__device__ __forceinline__ void mma1(float acc[4],
                                     float a0, float a1, float a2, float a3,
                                     float b0, float b1) {
    asm volatile(
        "mma.sync.aligned.m16n8k8.row.col.f32.tf32.tf32.f32 "
        "{%0,%1,%2,%3}, {%4,%5,%6,%7}, {%8,%9}, {%0,%1,%2,%3};\n"
        : "+f"(acc[0]), "+f"(acc[1]), "+f"(acc[2]), "+f"(acc[3])
        : "r"(__float_as_uint(a0)), "r"(__float_as_uint(a1)),
          "r"(__float_as_uint(a2)), "r"(__float_as_uint(a3)),
          "r"(__float_as_uint(b0)), "r"(__float_as_uint(b1)));
}

// warp 64x64 via smem A + smem B (N-tile = 8)
template <int BS>
__device__ __forceinline__ void mma_k8w(float acc[4][8][4],
                                        const float* As, const float* Bs,
                                        int kk, int wy, int wx, int lane) {
    int g = lane >> 2, t4 = lane & 3;
    float a[4][4];
#pragma unroll
    for (int mt = 0; mt < 4; mt++) {
        int rm = wy * 64 + mt * 16 + g;
        a[mt][0] = As[(kk + t4) * PA + rm];
        a[mt][1] = As[(kk + t4) * PA + rm + 8];
        a[mt][2] = As[(kk + t4 + 4) * PA + rm];
        a[mt][3] = As[(kk + t4 + 4) * PA + rm + 8];
    }
#pragma unroll
    for (int nt = 0; nt < 8; nt++) {
        int cn = wx * 64 + nt * 8 + g;
        float b0 = Bs[(kk + t4) * BS + cn];
        float b1 = Bs[(kk + t4 + 4) * BS + cn];
#pragma unroll
        for (int mt = 0; mt < 4; mt++)
            mma1(acc[mt][nt], a[mt][0], a[mt][1], a[mt][2], a[mt][3], b0, b1);
    }
}

// warp 64x32 (N-tile = 4) for fused out layer 2
__device__ __forceinline__ void mma_k8n4(float acc[4][4][4],
                                         const float* As, const float* Bs,
                                         int kk, int wy, int wx, int lane) {
    int g = lane >> 2, t4 = lane & 3;
    float a[4][4];
#pragma unroll
    for (int mt = 0; mt < 4; mt++) {
        int rm = wy * 64 + mt * 16 + g;
        a[mt][0] = As[(kk + t4) * PA + rm];
        a[mt][1] = As[(kk + t4) * PA + rm + 8];
        a[mt][2] = As[(kk + t4 + 4) * PA + rm];
        a[mt][3] = As[(kk + t4 + 4) * PA + rm + 8];
    }
#pragma unroll
    for (int nt = 0; nt < 4; nt++) {
        int cn = wx * 32 + nt * 8 + g;
        float b0 = Bs[(kk + t4) * PB1 + cn];
        float b1 = Bs[(kk + t4 + 4) * PB1 + cn];
#pragma unroll
        for (int mt = 0; mt < 4; mt++)
            mma1(acc[mt][nt], a[mt][0], a[mt][1], a[mt][2], a[mt][3], b0, b1);
    }
}

// B tile 16x256, 256 threads: thread owns COLUMN tid (conflict-free stores)
__device__ __forceinline__ void load_w256(float v[16], const float* __restrict__ W,
                                          int ldw, int k0, int tid) {
    const float* p = &W[(size_t)k0 * ldw + tid];
#pragma unroll
    for (int k = 0; k < 16; k++) v[k] = p[(size_t)k * ldw];
}
__device__ __forceinline__ void store_w256(float* Bs, const float v[16], int tid) {
#pragma unroll
    for (int k = 0; k < 16; k++) Bs[k * PB + tid] = totf(v[k]);
}
// A: 256 threads, r = tid&127, kh = (tid>>7)*8
__device__ __forceinline__ void store_a8(float* As, int kh, int r, const float v[8]) {
#pragma unroll
    for (int i = 0; i < 8; i++) As[(kh + i) * PA + r] = totf(v[i]);
}

// ---------------- temb (comb fused) -----------------------------------------
__global__ void __launch_bounds__(128)
temb_fused(const float* __restrict__ t, const float* __restrict__ fw,
           const float* __restrict__ tW, const float* __restrict__ tb,
           const float* __restrict__ d1W, const float* __restrict__ d1b) {
    __shared__ float d1S[H], combS[H + 1], red[128];
    int tid = threadIdx.x, lane = tid & 31, warp = tid >> 5;
    d1S[tid] = d1W[tid]; d1S[tid + 128] = d1W[tid + 128];
    __syncthreads();
    for (int row = warp; row < H + 1; row += 4) {
        const float* p = (row < H) ? &tW[(size_t)row * H] : tb;
        float s = 0.f;
        for (int k = lane; k < H; k += 32) s += p[k] * d1S[k];
#pragma unroll
        for (int o = 16; o; o >>= 1) s += __shfl_down_sync(0xffffffffu, s, o);
        if (lane == 0) combS[row] = (row == H) ? s + d1b[0] : s;
    }
    __syncthreads();
    int g = blockIdx.x;
    float tt = t[g];
    float xp = tt * fw[tid] * 6.283185307179586f;
    red[tid] = sinf(xp) * combS[tid] + cosf(xp) * combS[128 + tid];
    __syncthreads();
    for (int s = 64; s > 0; s >>= 1) {
        if (tid < s) red[tid] += red[tid + s];
        __syncthreads();
    }
    if (tid == 0) {
        g_temb[g] = red[0] + combS[H];
        const float LS = 3.2188758248682006f;   // ln(25)
        float var = (expf(2.f * tt * LS) - 1.f) / (2.f * LS);
        g_invstd[g] = rsqrtf(var);
    }
}

// ---------------- sort machinery ---------------------------------------------
__global__ void __launch_bounds__(256) hist(const int* __restrict__ dst) {
    int e = blockIdx.x * blockDim.x + threadIdx.x;
    if (e < EN) atomicAdd(&g_cnt[dst[e]], 1);
}

__global__ void __launch_bounds__(1024) scan_kernel() {
    __shared__ int part[1024];
    const int CH = 49;
    int t = threadIdx.x;
    int beg = t * CH, end = min(beg + CH, NN);
    int s = 0;
    for (int i = beg; i < end; i++) s += g_cnt[i];
    part[t] = s;
    __syncthreads();
    for (int off = 1; off < 1024; off <<= 1) {
        int v = (t >= off) ? part[t - off] : 0;
        __syncthreads();
        part[t] += v;
        __syncthreads();
    }
    int run = (t == 0) ? 0 : part[t - 1];
    for (int i = beg; i < end; i++) {
        g_rp[i] = run; g_woff[i] = run; run += g_cnt[i];
        g_cnt[i] = 0;
    }
    if (t == 1023) g_rp[NN] = part[1023];
}

__global__ void __launch_bounds__(256) place(const int* __restrict__ src,
                                             const int* __restrict__ dst) {
    int e = blockIdx.x * blockDim.x + threadIdx.x;
    if (e >= EN) return;
    int p = atomicAdd(&g_woff[dst[e]], 1);
    g_srcp[p] = src[e];
    g_eid[p] = e;
}

__global__ void __launch_bounds__(256) init_h(const int* __restrict__ nt,
                                              const float* __restrict__ atom_emb) {
    int idx = blockIdx.x * blockDim.x + threadIdx.x;
    if (idx >= NN * 64) return;
    int n = idx >> 6, q = idx & 63;
    ((float4*)g_h)[idx] = ((const float4*)atom_emb)[nt[n] * 64 + q];
}

// ---------------- gather: aggr[n] = sum relu(h[src]+bond) -------------------
__global__ void __launch_bounds__(256) gather() {
    int warp = threadIdx.x >> 5, lane = threadIdx.x & 31;
    int n = blockIdx.x * 8 + warp;
    if (n >= NN) return;
    int q = lane * 8;
    float4 a0 = make_float4(0.f, 0.f, 0.f, 0.f), a1 = a0;
    int beg = g_rp[n], end = g_rp[n + 1];
    for (int p = beg; p < end; p++) {
        int s = g_srcp[p];
        int e = g_eid[p];
        const float4* hp = (const float4*)&g_h[s * H + q];
        const float4* bp = (const float4*)&g_bond[(size_t)e * H + q];
        float4 h0 = hp[0], h1v = hp[1], b0 = bp[0], b1v = bp[1];
        a0.x += fmaxf(h0.x + b0.x, 0.f);  a0.y += fmaxf(h0.y + b0.y, 0.f);
        a0.z += fmaxf(h0.z + b0.z, 0.f);  a0.w += fmaxf(h0.w + b0.w, 0.f);
        a1.x += fmaxf(h1v.x + b1v.x, 0.f); a1.y += fmaxf(h1v.y + b1v.y, 0.f);
        a1.z += fmaxf(h1v.z + b1v.z, 0.f); a1.w += fmaxf(h1v.w + b1v.w, 0.f);
    }
    float4* ap = (float4*)&g_aggr[n * H + q];
    ap[0] = a0; ap[1] = a1;
}

// ---------------- edge_bond: A fragments computed in registers --------------
#define ASZ (16 * PA)
#define BSZ (16 * PB)
#define EB_SMEM ((2 * BSZ + 128 + 128 + 128 + 2 * H) * 4)

__global__ void __launch_bounds__(256, 1)
edge_bond(const float* __restrict__ elen, const int* __restrict__ src,
          const int* __restrict__ batch, const int* __restrict__ etype,
          const float* __restrict__ W1, const float* __restrict__ b1,
          const float* __restrict__ W2, const float* __restrict__ b2,
          const float* __restrict__ bond_emb) {
    extern __shared__ float sm[];
    float* Bs = sm;                       // 2*BSZ
    float* xS = Bs + 2 * BSZ;             // 128
    float* tS = xS + 128;                 // 128
    int*   eS = (int*)(tS + 128);         // 128
    float* w1S = (float*)(eS + 128);      // 256
    float* b1S = w1S + H;                 // 256

    int tid = threadIdx.x, lane = tid & 31, warp = tid >> 5;
    int wy = warp >> 2, wx = warp & 3;
    int g = lane >> 2, t4 = lane & 3;
    int m0 = blockIdx.x * 128;

    if (tid < 128) {
        int e = m0 + tid;
        float x = 0.f, tb = 0.f; int et = 0;
        if (e < EN) {
            x = elen[e];
            int gph = batch[src[e]];
            tb = g_temb[gph];
            g_einv[e] = g_invstd[gph];
            et = etype[e];
        }
        xS[tid] = x; tS[tid] = tb; eS[tid] = et;
    }
    w1S[tid] = W1[tid]; b1S[tid] = b1[tid];
    __syncthreads();

    // preload this thread's 8 A-rows' x values
    float xr[4][2];
#pragma unroll
    for (int mt = 0; mt < 4; mt++) {
        xr[mt][0] = xS[wy * 64 + mt * 16 + g];
        xr[mt][1] = xS[wy * 64 + mt * 16 + g + 8];
    }

    float breg[16];
    load_w256(breg, W2, H, 0, tid);
    store_w256(Bs, breg, tid);
    __syncthreads();

    float acc[4][8][4] = {};
    for (int s = 0; s < 16; s++) {
        int cur = s & 1, nxt = cur ^ 1;
        if (s < 15) load_w256(breg, W2, H, (s + 1) * 16, tid);
        const float* B = Bs + cur * BSZ;
#pragma unroll
        for (int kh = 0; kh < 16; kh += 8) {
            int kA = s * 16 + kh;
            float w0 = w1S[kA + t4], w4 = w1S[kA + t4 + 4];
            float c0 = b1S[kA + t4], c4 = b1S[kA + t4 + 4];
            float a[4][4];
#pragma unroll
            for (int mt = 0; mt < 4; mt++) {
                a[mt][0] = totf(fmaxf(fmaf(xr[mt][0], w0, c0), 0.f));
                a[mt][1] = totf(fmaxf(fmaf(xr[mt][1], w0, c0), 0.f));
                a[mt][2] = totf(fmaxf(fmaf(xr[mt][0], w4, c4), 0.f));
                a[mt][3] = totf(fmaxf(fmaf(xr[mt][1], w4, c4), 0.f));
            }
#pragma unroll
            for (int nt = 0; nt < 8; nt++) {
                int cn = wx * 64 + nt * 8 + g;
                float b0 = B[(kh + t4) * PB + cn];
                float b1v = B[(kh + t4 + 4) * PB + cn];
#pragma unroll
                for (int mt = 0; mt < 4; mt++)
                    mma1(acc[mt][nt], a[mt][0], a[mt][1], a[mt][2], a[mt][3], b0, b1v);
            }
        }
        if (s < 15) {
            store_w256(Bs + nxt * BSZ, breg, tid);
            __syncthreads();
        }
    }

#pragma unroll
    for (int mt = 0; mt < 4; mt++)
#pragma unroll
        for (int half = 0; half < 2; half++) {
            int rl = wy * 64 + mt * 16 + g + half * 8;
            int row = m0 + rl;
            if (row >= EN) continue;
            float tb = tS[rl];
            const float* bep = &bond_emb[eS[rl] * H];
            size_t obase = (size_t)row * H;
#pragma unroll
            for (int nt = 0; nt < 8; nt++) {
                int col = wx * 64 + nt * 8 + 2 * t4;
                float v0 = (acc[mt][nt][half * 2 + 0] + b2[col] + tb) * bep[col];
                float v1 = (acc[mt][nt][half * 2 + 1] + b2[col + 1] + tb) * bep[col + 1];
                *(float2*)&g_bond[obase + col] = make_float2(v0, v1);
            }
        }
}

// ---------------- GIN GEMMs: 128x256 tile, pipelined ------------------------
#define GIN_SMEM ((2 * ASZ + 2 * BSZ) * 4)
template <int MODE>
__global__ void __launch_bounds__(256, 1)
gin_mma(const float* __restrict__ W, const float* __restrict__ bias, int reluOut) {
    extern __shared__ float sm[];
    float* As = sm;
    float* Bs = sm + 2 * ASZ;
    int tid = threadIdx.x, lane = tid & 31, warp = tid >> 5;
    int wy = warp >> 2, wx = warp & 3;
    int m0 = blockIdx.x * 128;
    int r = tid & 127, kh = (tid >> 7) * 8;
    int arow = m0 + r;
    bool valid = (arow < NN);
    const float* A1 = (MODE == 0) ? g_h : g_tmp;

    float areg[8], breg[16];
    auto loadA = [&](int k0) {
        if (valid) {
            const float* p = &A1[arow * H + k0 + kh];
            float4 v0 = *(const float4*)p, v1 = *(const float4*)(p + 4);
            areg[0] = v0.x; areg[1] = v0.y; areg[2] = v0.z; areg[3] = v0.w;
            areg[4] = v1.x; areg[5] = v1.y; areg[6] = v1.z; areg[7] = v1.w;
            if (MODE == 0) {
                const float* q = &g_aggr[arow * H + k0 + kh];
                float4 w0 = *(const float4*)q, w1 = *(const float4*)(q + 4);
                areg[0] += w0.x; areg[1] += w0.y; areg[2] += w0.z; areg[3] += w0.w;
                areg[4] += w1.x; areg[5] += w1.y; areg[6] += w1.z; areg[7] += w1.w;
            }
        } else {
#pragma unroll
            for (int i = 0; i < 8; i++) areg[i] = 0.f;
        }
    };

    loadA(0);
    load_w256(breg, W, H, 0, tid);
    store_a8(As, kh, r, areg);
    store_w256(Bs, breg, tid);
    __syncthreads();

    float acc[4][8][4] = {};
    for (int s = 0; s < 16; s++) {
        int cur = s & 1, nxt = cur ^ 1;
        if (s < 15) { loadA((s + 1) * 16); load_w256(breg, W, H, (s + 1) * 16, tid); }
        mma_k8w<PB>(acc, As + cur * ASZ, Bs + cur * BSZ, 0, wy, wx, lane);
        mma_k8w<PB>(acc, As + cur * ASZ, Bs + cur * BSZ, 8, wy, wx, lane);
        if (s < 15) {
            store_a8(As + nxt * ASZ, kh, r, areg);
            store_w256(Bs + nxt * BSZ, breg, tid);
            __syncthreads();
        }
    }

    int g = lane >> 2, t4 = lane & 3;
#pragma unroll
    for (int mt = 0; mt < 4; mt++)
#pragma unroll
        for (int half = 0; half < 2; half++) {
            int row = m0 + wy * 64 + mt * 16 + g + half * 8;
            if (row >= NN) continue;
#pragma unroll
            for (int nt = 0; nt < 8; nt++) {
                int col = wx * 64 + nt * 8 + 2 * t4;
                float v0 = acc[mt][nt][half * 2 + 0] + bias[col];
                float v1 = acc[mt][nt][half * 2 + 1] + bias[col + 1];
                if (reluOut) { v0 = fmaxf(v0, 0.f); v1 = fmaxf(v1, 0.f); }
                if (MODE == 0) {
                    *(float2*)&g_tmp[row * H + col] = make_float2(v0, v1);
                } else {
                    float2 rh = *(const float2*)&g_h[row * H + col];
                    *(float2*)&g_h[row * H + col] = make_float2(v0 + rh.x, v1 + rh.y);
                }
            }
        }
}

// ---------------- out_fused: layers 1+2+3 in one kernel ---------------------
// phase1: acc = feat[128,512] @ W1 (pipelined), phase2: h2 via 16 k-chunks
// through smem from acc, phase3: dot W3, scale by 1/std.
#define OUT_SMEM ((2 * ASZ + 2 * BSZ + 256) * 4)
__global__ void __launch_bounds__(256, 1)
out_fused(const int* __restrict__ src, const int* __restrict__ dst,
          const float* __restrict__ W1, const float* __restrict__ b1,
          const float* __restrict__ W2, const float* __restrict__ b2,
          const float* __restrict__ W3, const float* __restrict__ b3,
          float* __restrict__ out) {
    extern __shared__ float sm[];
    float* As = sm;                     // phase1: 2*ASZ; phase2: chunk A; phase3: red
    float* Bs = sm + 2 * ASZ;           // phase1: 2*BSZ; phase2: W2 chunk
    int* srcS = (int*)(Bs + 2 * BSZ);   // 128
    int* dstS = srcS + 128;             // 128
    int tid = threadIdx.x, lane = tid & 31, warp = tid >> 5;
    int wy = warp >> 2, wx = warp & 3;
    int g = lane >> 2, t4 = lane & 3;
    int m0 = blockIdx.x * 128;

    if (tid < 128) {
        int e = m0 + tid;
        int s = 0, d = 0;
        if (e < EN) { s = src[e]; d = dst[e]; }
        srcS[tid] = s; dstS[tid] = d;
    }
    __syncthreads();

    int r = tid & 127, kh = (tid >> 7) * 8;
    int er = m0 + r;
    bool validr = (er < EN);
    float areg[8], breg[16];

    auto loadA = [&](int k0) {
        if (k0 < 256) {
            const float* hs = &g_h[srcS[r] * H + k0 + kh];
            const float* hd = &g_h[dstS[r] * H + k0 + kh];
            float4 a0 = *(const float4*)hs, a1 = *(const float4*)(hs + 4);
            float4 c0 = *(const float4*)hd, c1 = *(const float4*)(hd + 4);
            areg[0] = a0.x * c0.x; areg[1] = a0.y * c0.y;
            areg[2] = a0.z * c0.z; areg[3] = a0.w * c0.w;
            areg[4] = a1.x * c1.x; areg[5] = a1.y * c1.y;
            areg[6] = a1.z * c1.z; areg[7] = a1.w * c1.w;
        } else if (validr) {
            const float* bp = &g_bond[(size_t)er * H + (k0 - 256) + kh];
            float4 v0 = *(const float4*)bp, v1 = *(const float4*)(bp + 4);
            areg[0] = v0.x; areg[1] = v0.y; areg[2] = v0.z; areg[3] = v0.w;
            areg[4] = v1.x; areg[5] = v1.y; areg[6] = v1.z; areg[7] = v1.w;
        } else {
#pragma unroll
            for (int i = 0; i < 8; i++) areg[i] = 0.f;
        }
    };

    loadA(0);
    load_w256(breg, W1, H, 0, tid);
    store_a8(As, kh, r, areg);
    store_w256(Bs, breg, tid);
    __syncthreads();

    float acc[4][8][4] = {};
    for (int s = 0; s < 32; s++) {
        int cur = s & 1, nxt = cur ^ 1;
        if (s < 31) { loadA((s + 1) * 16); load_w256(breg, W1, H, (s + 1) * 16, tid); }
        mma_k8w<PB>(acc, As + cur * ASZ, Bs + cur * BSZ, 0, wy, wx, lane);
        mma_k8w<PB>(acc, As + cur * ASZ, Bs + cur * BSZ, 8, wy, wx, lane);
        if (s < 31) {
            store_a8(As + nxt * ASZ, kh, r, areg);
            store_w256(Bs + nxt * BSZ, breg, tid);
            __syncthreads();
        }
    }

    // ---- phase 2: h2 = relu(h1 @ W2 + b2), h1 streamed from acc via smem ---
    float acc2[4][4][4] = {};
    for (int chunk = 0; chunk < 16; chunk++) {
        int kc = chunk * 16;
        __syncthreads();   // previous chunk reads (or phase-1 mma) done
        // owner warps (wx == kc>>6) export 16 h1 columns, bias+relu applied
        if (wx == (kc >> 6)) {
            int nt0 = (kc & 63) >> 3;
#pragma unroll
            for (int mt = 0; mt < 4; mt++)
#pragma unroll
                for (int half = 0; half < 2; half++) {
                    int rl = wy * 64 + mt * 16 + g + half * 8;
#pragma unroll
                    for (int q = 0; q < 2; q++) {
                        int nt = nt0 + q;
#pragma unroll
                        for (int j = 0; j < 2; j++) {
                            int c = wx * 64 + nt * 8 + 2 * t4 + j;
                            float v = fmaxf(acc[mt][nt][half * 2 + j] + b1[c], 0.f);
                            As[(c - kc) * PA + rl] = totf(v);
                        }
                    }
                }
        }
        // W2 chunk [kc..kc+16) x 128 -> Bs (PB1 stride), column-per-thread
        if (tid < 128) {
#pragma unroll
            for (int k = 0; k < 16; k++)
                Bs[k * PB1 + tid] = totf(W2[(size_t)(kc + k) * 128 + tid]);
        }
        __syncthreads();
        mma_k8n4(acc2, As, Bs, 0, wy, wx, lane);
        mma_k8n4(acc2, As, Bs, 8, wy, wx, lane);
    }

    // ---- phase 3: score = relu(h2 + b2) . W3, scaled ----
    __syncthreads();
    float* red = As;   // 128*16 floats, fits in ASZ*2
#pragma unroll
    for (int mt = 0; mt < 4; mt++)
#pragma unroll
        for (int half = 0; half < 2; half++) {
            int rl = wy * 64 + mt * 16 + g + half * 8;
            float partial = 0.f;
#pragma unroll
            for (int nt = 0; nt < 4; nt++) {
#pragma unroll
                for (int j = 0; j < 2; j++) {
                    int c = wx * 32 + nt * 8 + 2 * t4 + j;
                    float h = fmaxf(acc2[mt][nt][half * 2 + j] + b2[c], 0.f);
                    partial += h * W3[c];
                }
            }
            red[rl * 16 + wx * 4 + t4] = partial;
        }
    __syncthreads();

    if (tid < 128) {
        int e = m0 + tid;
        if (e < EN) {
            float s = 0.f;
#pragma unroll
            for (int i = 0; i < 16; i++) s += red[tid * 16 + i];
            out[e] = (s + b3[0]) * g_einv[e];
        }
    }
}

// ---------------- launch ----------------------------------------------------
extern "C" void kernel_launch(void* const* d_in, const int* in_sizes, int n_in,
                              void* d_out, int out_size) {
    const int*   node_type = (const int*)d_in[0];
    const int*   edge_type = (const int*)d_in[1];
    const int*   edge_index = (const int*)d_in[2];
    const int*   batch = (const int*)d_in[3];
    const float* elen = (const float*)d_in[4];
    const float* t = (const float*)d_in[5];
    const float* atom_emb = (const float*)d_in[6];
    const float* bond_emb = (const float*)d_in[7];
    const float* in_W1 = (const float*)d_in[8];
    const float* in_b1 = (const float*)d_in[9];
    const float* in_W2 = (const float*)d_in[10];
    const float* in_b2 = (const float*)d_in[11];
    const float* fourier_W = (const float*)d_in[12];
    const float* temb_W = (const float*)d_in[13];
    const float* temb_b = (const float*)d_in[14];
    const float* d1W = (const float*)d_in[15];
    const float* d1b = (const float*)d_in[16];
    const float* gin_W1 = (const float*)d_in[17];
    const float* gin_b1 = (const float*)d_in[18];
    const float* gin_W2 = (const float*)d_in[19];
    const float* gin_b2 = (const float*)d_in[20];
    const float* out_W1 = (const float*)d_in[21];
    const float* out_b1 = (const float*)d_in[22];
    const float* out_W2 = (const float*)d_in[23];
    const float* out_b2 = (const float*)d_in[24];
    const float* out_W3 = (const float*)d_in[25];
    const float* out_b3 = (const float*)d_in[26];
    const int* src = edge_index;
    const int* dst = edge_index + EN;
    float* out = (float*)d_out;

    const int EB = (EN + 127) / 128;   // 2344
    const int NB = (NN + 127) / 128;   // 391

    static int attr_done = 0;
    if (!attr_done) {
        cudaFuncSetAttribute(edge_bond, cudaFuncAttributeMaxDynamicSharedMemorySize, EB_SMEM);
        cudaFuncSetAttribute(gin_mma<0>, cudaFuncAttributeMaxDynamicSharedMemorySize, GIN_SMEM);
        cudaFuncSetAttribute(gin_mma<1>, cudaFuncAttributeMaxDynamicSharedMemorySize, GIN_SMEM);
        cudaFuncSetAttribute(out_fused, cudaFuncAttributeMaxDynamicSharedMemorySize, OUT_SMEM);
        attr_done = 1;
    }

    // launch order chosen so ncu (launch index 3) profiles edge_bond
    temb_fused<<<GN, 128>>>(t, fourier_W, temb_W, temb_b, d1W, d1b);      // 0
    hist<<<(EN + 255) / 256, 256>>>(dst);                                 // 1
    scan_kernel<<<1, 1024>>>();                                           // 2
    edge_bond<<<EB, 256, EB_SMEM>>>(elen, src, batch, edge_type,          // 3
                                    in_W1, in_b1, in_W2, in_b2, bond_emb);
    place<<<(EN + 255) / 256, 256>>>(src, dst);                           // 4
    init_h<<<(NN * 64 + 255) / 256, 256>>>(node_type, atom_emb);          // 5

    for (int c = 0; c < NCONV; c++) {
        gather<<<(NN + 7) / 8, 256>>>();
        gin_mma<0><<<NB, 256, GIN_SMEM>>>(gin_W1 + c * H * H, gin_b1 + c * H, 1);
        gin_mma<1><<<NB, 256, GIN_SMEM>>>(gin_W2 + c * H * H, gin_b2 + c * H,
                                          (c < NCONV - 1) ? 1 : 0);
    }

    out_fused<<<EB, 256, OUT_SMEM>>>(src, dst, out_W1, out_b1,
                                     out_W2, out_b2, out_W3, out_b3, out);
}

// round 10
// speedup vs baseline: 1.8997x; 1.8997x over previous
#include <cuda_runtime.h>
#include <math.h>
#include <stdint.h>

#define EN 300000
#define NN 50000
#define GN 1024
#define H  256
#define NCONV 4
#define PA 136      // A smem row stride: 136 mod 32 == 8 -> conflict-free frag loads
#define PB 264      // B smem row stride (256-wide tiles)
#define PB1 136     // B smem row stride (128-wide tiles)

// ---------------- scratch (device globals) ---------------------------------
static __device__ float g_bond[(size_t)EN * H];   // bond_attr [E,H] (edge order)
static __device__ float g_h1[(size_t)EN * H];     // out-MLP hidden1
static __device__ float g_h[NN * H];
static __device__ float g_aggr[NN * H];
static __device__ float g_tmp[NN * H];
static __device__ float g_temb[GN];
static __device__ float g_invstd[GN];
static __device__ float g_einv[EN];
// sort machinery
static __device__ int g_cnt[NN];      // zero-init; scan re-zeroes each call
static __device__ int g_rp[NN + 1];
static __device__ int g_woff[NN];
static __device__ int g_srcp[EN];
static __device__ int g_eid[EN];

// ---------------- helpers ---------------------------------------------------
__device__ __forceinline__ float totf(float x) {
    uint32_t u; asm("cvt.rna.tf32.f32 %0, %1;" : "=r"(u) : "f"(x));
    return __uint_as_float(u);
}

__device__ __forceinline__ void mma1(float acc[4],
                                     float a0, float a1, float a2, float a3,
                                     float b0, float b1) {
    asm volatile(
        "mma.sync.aligned.m16n8k8.row.col.f32.tf32.tf32.f32 "
        "{%0,%1,%2,%3}, {%4,%5,%6,%7}, {%8,%9}, {%0,%1,%2,%3};\n"
        : "+f"(acc[0]), "+f"(acc[1]), "+f"(acc[2]), "+f"(acc[3])
        : "r"(__float_as_uint(a0)), "r"(__float_as_uint(a1)),
          "r"(__float_as_uint(a2)), "r"(__float_as_uint(a3)),
          "r"(__float_as_uint(b0)), "r"(__float_as_uint(b1)));
}

// warp 64x64 via smem A + smem B (N-tile = 8)
template <int BS>
__device__ __forceinline__ void mma_k8w(float acc[4][8][4],
                                        const float* As, const float* Bs,
                                        int kk, int wy, int wx, int lane) {
    int g = lane >> 2, t4 = lane & 3;
    float a[4][4];
#pragma unroll
    for (int mt = 0; mt < 4; mt++) {
        int rm = wy * 64 + mt * 16 + g;
        a[mt][0] = As[(kk + t4) * PA + rm];
        a[mt][1] = As[(kk + t4) * PA + rm + 8];
        a[mt][2] = As[(kk + t4 + 4) * PA + rm];
        a[mt][3] = As[(kk + t4 + 4) * PA + rm + 8];
    }
#pragma unroll
    for (int nt = 0; nt < 8; nt++) {
        int cn = wx * 64 + nt * 8 + g;
        float b0 = Bs[(kk + t4) * BS + cn];
        float b1 = Bs[(kk + t4 + 4) * BS + cn];
#pragma unroll
        for (int mt = 0; mt < 4; mt++)
            mma1(acc[mt][nt], a[mt][0], a[mt][1], a[mt][2], a[mt][3], b0, b1);
    }
}

// B tile 16x256, 256 threads: thread owns COLUMN tid (conflict-free stores)
__device__ __forceinline__ void load_w256(float v[16], const float* __restrict__ W,
                                          int ldw, int k0, int tid) {
    const float* p = &W[(size_t)k0 * ldw + tid];
#pragma unroll
    for (int k = 0; k < 16; k++) v[k] = p[(size_t)k * ldw];
}
__device__ __forceinline__ void store_w256(float* Bs, const float v[16], int tid) {
#pragma unroll
    for (int k = 0; k < 16; k++) Bs[k * PB + tid] = totf(v[k]);
}
// B tile 16x128, 128 threads: thread owns column tid
__device__ __forceinline__ void load_w128(float v[16], const float* __restrict__ W,
                                          int ldw, int k0, int tid) {
    const float* p = &W[(size_t)k0 * ldw + tid];
#pragma unroll
    for (int k = 0; k < 16; k++) v[k] = p[(size_t)k * ldw];
}
__device__ __forceinline__ void store_w128(float* Bs, const float v[16], int tid) {
#pragma unroll
    for (int k = 0; k < 16; k++) Bs[k * PB1 + tid] = totf(v[k]);
}
// A: 256 threads, r = tid&127, kh = (tid>>7)*8
__device__ __forceinline__ void store_a8(float* As, int kh, int r, const float v[8]) {
#pragma unroll
    for (int i = 0; i < 8; i++) As[(kh + i) * PA + r] = totf(v[i]);
}
// A: 128 threads, 16 k's of row tid
__device__ __forceinline__ void store_a16(float* As, int r, const float v[16]) {
#pragma unroll
    for (int k = 0; k < 16; k++) As[k * PA + r] = totf(v[k]);
}

// ---------------- temb (comb fused) -----------------------------------------
__global__ void __launch_bounds__(128)
temb_fused(const float* __restrict__ t, const float* __restrict__ fw,
           const float* __restrict__ tW, const float* __restrict__ tb,
           const float* __restrict__ d1W, const float* __restrict__ d1b) {
    __shared__ float d1S[H], combS[H + 1], red[128];
    int tid = threadIdx.x, lane = tid & 31, warp = tid >> 5;
    d1S[tid] = d1W[tid]; d1S[tid + 128] = d1W[tid + 128];
    __syncthreads();
    for (int row = warp; row < H + 1; row += 4) {
        const float* p = (row < H) ? &tW[(size_t)row * H] : tb;
        float s = 0.f;
        for (int k = lane; k < H; k += 32) s += p[k] * d1S[k];
#pragma unroll
        for (int o = 16; o; o >>= 1) s += __shfl_down_sync(0xffffffffu, s, o);
        if (lane == 0) combS[row] = (row == H) ? s + d1b[0] : s;
    }
    __syncthreads();
    int g = blockIdx.x;
    float tt = t[g];
    float xp = tt * fw[tid] * 6.283185307179586f;
    red[tid] = sinf(xp) * combS[tid] + cosf(xp) * combS[128 + tid];
    __syncthreads();
    for (int s = 64; s > 0; s >>= 1) {
        if (tid < s) red[tid] += red[tid + s];
        __syncthreads();
    }
    if (tid == 0) {
        g_temb[g] = red[0] + combS[H];
        const float LS = 3.2188758248682006f;   // ln(25)
        float var = (expf(2.f * tt * LS) - 1.f) / (2.f * LS);
        g_invstd[g] = rsqrtf(var);
    }
}

// ---------------- sort machinery ---------------------------------------------
__global__ void __launch_bounds__(256) hist(const int* __restrict__ dst) {
    int e = blockIdx.x * blockDim.x + threadIdx.x;
    if (e < EN) atomicAdd(&g_cnt[dst[e]], 1);
}

__global__ void __launch_bounds__(1024) scan_kernel() {
    __shared__ int part[1024];
    const int CH = 49;
    int t = threadIdx.x;
    int beg = t * CH, end = min(beg + CH, NN);
    int s = 0;
    for (int i = beg; i < end; i++) s += g_cnt[i];
    part[t] = s;
    __syncthreads();
    for (int off = 1; off < 1024; off <<= 1) {
        int v = (t >= off) ? part[t - off] : 0;
        __syncthreads();
        part[t] += v;
        __syncthreads();
    }
    int run = (t == 0) ? 0 : part[t - 1];
    for (int i = beg; i < end; i++) {
        g_rp[i] = run; g_woff[i] = run; run += g_cnt[i];
        g_cnt[i] = 0;
    }
    if (t == 1023) g_rp[NN] = part[1023];
}

__global__ void __launch_bounds__(256) place(const int* __restrict__ src,
                                             const int* __restrict__ dst) {
    int e = blockIdx.x * blockDim.x + threadIdx.x;
    if (e >= EN) return;
    int p = atomicAdd(&g_woff[dst[e]], 1);
    g_srcp[p] = src[e];
    g_eid[p] = e;
}

__global__ void __launch_bounds__(256) init_h(const int* __restrict__ nt,
                                              const float* __restrict__ atom_emb) {
    int idx = blockIdx.x * blockDim.x + threadIdx.x;
    if (idx >= NN * 64) return;
    int n = idx >> 6, q = idx & 63;
    ((float4*)g_h)[idx] = ((const float4*)atom_emb)[nt[n] * 64 + q];
}

// ---------------- gather: aggr[n] = sum relu(h[src]+bond) -------------------
__global__ void __launch_bounds__(256) gather() {
    int warp = threadIdx.x >> 5, lane = threadIdx.x & 31;
    int n = blockIdx.x * 8 + warp;
    if (n >= NN) return;
    int q = lane * 8;
    float4 a0 = make_float4(0.f, 0.f, 0.f, 0.f), a1 = a0;
    int beg = g_rp[n], end = g_rp[n + 1];
    for (int p = beg; p < end; p++) {
        int s = g_srcp[p];
        int e = g_eid[p];
        const float4* hp = (const float4*)&g_h[s * H + q];
        const float4* bp = (const float4*)&g_bond[(size_t)e * H + q];
        float4 h0 = hp[0], h1v = hp[1], b0 = bp[0], b1v = bp[1];
        a0.x += fmaxf(h0.x + b0.x, 0.f);  a0.y += fmaxf(h0.y + b0.y, 0.f);
        a0.z += fmaxf(h0.z + b0.z, 0.f);  a0.w += fmaxf(h0.w + b0.w, 0.f);
        a1.x += fmaxf(h1v.x + b1v.x, 0.f); a1.y += fmaxf(h1v.y + b1v.y, 0.f);
        a1.z += fmaxf(h1v.z + b1v.z, 0.f); a1.w += fmaxf(h1v.w + b1v.w, 0.f);
    }
    float4* ap = (float4*)&g_aggr[n * H + q];
    ap[0] = a0; ap[1] = a1;
}

// ---------------- edge_bond: A fragments computed in registers --------------
#define ASZ (16 * PA)
#define BSZ (16 * PB)
#define EB_SMEM ((2 * BSZ + 128 + 128 + 128 + 2 * H) * 4)

__global__ void __launch_bounds__(256, 1)
edge_bond(const float* __restrict__ elen, const int* __restrict__ src,
          const int* __restrict__ batch, const int* __restrict__ etype,
          const float* __restrict__ W1, const float* __restrict__ b1,
          const float* __restrict__ W2, const float* __restrict__ b2,
          const float* __restrict__ bond_emb) {
    extern __shared__ float sm[];
    float* Bs = sm;                       // 2*BSZ
    float* xS = Bs + 2 * BSZ;             // 128
    float* tS = xS + 128;                 // 128
    int*   eS = (int*)(tS + 128);         // 128
    float* w1S = (float*)(eS + 128);      // 256
    float* b1S = w1S + H;                 // 256

    int tid = threadIdx.x, lane = tid & 31, warp = tid >> 5;
    int wy = warp >> 2, wx = warp & 3;
    int g = lane >> 2, t4 = lane & 3;
    int m0 = blockIdx.x * 128;

    if (tid < 128) {
        int e = m0 + tid;
        float x = 0.f, tb = 0.f; int et = 0;
        if (e < EN) {
            x = elen[e];
            int gph = batch[src[e]];
            tb = g_temb[gph];
            g_einv[e] = g_invstd[gph];
            et = etype[e];
        }
        xS[tid] = x; tS[tid] = tb; eS[tid] = et;
    }
    w1S[tid] = W1[tid]; b1S[tid] = b1[tid];
    __syncthreads();

    // preload this thread's 8 A-rows' x values
    float xr[4][2];
#pragma unroll
    for (int mt = 0; mt < 4; mt++) {
        xr[mt][0] = xS[wy * 64 + mt * 16 + g];
        xr[mt][1] = xS[wy * 64 + mt * 16 + g + 8];
    }

    float breg[16];
    load_w256(breg, W2, H, 0, tid);
    store_w256(Bs, breg, tid);
    __syncthreads();

    float acc[4][8][4] = {};
    for (int s = 0; s < 16; s++) {
        int cur = s & 1, nxt = cur ^ 1;
        if (s < 15) load_w256(breg, W2, H, (s + 1) * 16, tid);
        const float* B = Bs + cur * BSZ;
#pragma unroll
        for (int kh = 0; kh < 16; kh += 8) {
            int kA = s * 16 + kh;
            float w0 = w1S[kA + t4], w4 = w1S[kA + t4 + 4];
            float c0 = b1S[kA + t4], c4 = b1S[kA + t4 + 4];
            float a[4][4];
#pragma unroll
            for (int mt = 0; mt < 4; mt++) {
                a[mt][0] = totf(fmaxf(fmaf(xr[mt][0], w0, c0), 0.f));
                a[mt][1] = totf(fmaxf(fmaf(xr[mt][1], w0, c0), 0.f));
                a[mt][2] = totf(fmaxf(fmaf(xr[mt][0], w4, c4), 0.f));
                a[mt][3] = totf(fmaxf(fmaf(xr[mt][1], w4, c4), 0.f));
            }
#pragma unroll
            for (int nt = 0; nt < 8; nt++) {
                int cn = wx * 64 + nt * 8 + g;
                float b0 = B[(kh + t4) * PB + cn];
                float b1v = B[(kh + t4 + 4) * PB + cn];
#pragma unroll
                for (int mt = 0; mt < 4; mt++)
                    mma1(acc[mt][nt], a[mt][0], a[mt][1], a[mt][2], a[mt][3], b0, b1v);
            }
        }
        if (s < 15) {
            store_w256(Bs + nxt * BSZ, breg, tid);
            __syncthreads();
        }
    }

#pragma unroll
    for (int mt = 0; mt < 4; mt++)
#pragma unroll
        for (int half = 0; half < 2; half++) {
            int rl = wy * 64 + mt * 16 + g + half * 8;
            int row = m0 + rl;
            if (row >= EN) continue;
            float tb = tS[rl];
            const float* bep = &bond_emb[eS[rl] * H];
            size_t obase = (size_t)row * H;
#pragma unroll
            for (int nt = 0; nt < 8; nt++) {
                int col = wx * 64 + nt * 8 + 2 * t4;
                float v0 = (acc[mt][nt][half * 2 + 0] + b2[col] + tb) * bep[col];
                float v1 = (acc[mt][nt][half * 2 + 1] + b2[col + 1] + tb) * bep[col + 1];
                *(float2*)&g_bond[obase + col] = make_float2(v0, v1);
            }
        }
}

// ---------------- GIN GEMMs: 128x256 tile, pipelined ------------------------
#define GIN_SMEM ((2 * ASZ + 2 * BSZ) * 4)
template <int MODE>
__global__ void __launch_bounds__(256, 1)
gin_mma(const float* __restrict__ W, const float* __restrict__ bias, int reluOut) {
    extern __shared__ float sm[];
    float* As = sm;
    float* Bs = sm + 2 * ASZ;
    int tid = threadIdx.x, lane = tid & 31, warp = tid >> 5;
    int wy = warp >> 2, wx = warp & 3;
    int m0 = blockIdx.x * 128;
    int r = tid & 127, kh = (tid >> 7) * 8;
    int arow = m0 + r;
    bool valid = (arow < NN);
    const float* A1 = (MODE == 0) ? g_h : g_tmp;

    float areg[8], breg[16];
    auto loadA = [&](int k0) {
        if (valid) {
            const float* p = &A1[arow * H + k0 + kh];
            float4 v0 = *(const float4*)p, v1 = *(const float4*)(p + 4);
            areg[0] = v0.x; areg[1] = v0.y; areg[2] = v0.z; areg[3] = v0.w;
            areg[4] = v1.x; areg[5] = v1.y; areg[6] = v1.z; areg[7] = v1.w;
            if (MODE == 0) {
                const float* q = &g_aggr[arow * H + k0 + kh];
                float4 w0 = *(const float4*)q, w1 = *(const float4*)(q + 4);
                areg[0] += w0.x; areg[1] += w0.y; areg[2] += w0.z; areg[3] += w0.w;
                areg[4] += w1.x; areg[5] += w1.y; areg[6] += w1.z; areg[7] += w1.w;
            }
        } else {
#pragma unroll
            for (int i = 0; i < 8; i++) areg[i] = 0.f;
        }
    };

    loadA(0);
    load_w256(breg, W, H, 0, tid);
    store_a8(As, kh, r, areg);
    store_w256(Bs, breg, tid);
    __syncthreads();

    float acc[4][8][4] = {};
    for (int s = 0; s < 16; s++) {
        int cur = s & 1, nxt = cur ^ 1;
        if (s < 15) { loadA((s + 1) * 16); load_w256(breg, W, H, (s + 1) * 16, tid); }
        mma_k8w<PB>(acc, As + cur * ASZ, Bs + cur * BSZ, 0, wy, wx, lane);
        mma_k8w<PB>(acc, As + cur * ASZ, Bs + cur * BSZ, 8, wy, wx, lane);
        if (s < 15) {
            store_a8(As + nxt * ASZ, kh, r, areg);
            store_w256(Bs + nxt * BSZ, breg, tid);
            __syncthreads();
        }
    }

    int g = lane >> 2, t4 = lane & 3;
#pragma unroll
    for (int mt = 0; mt < 4; mt++)
#pragma unroll
        for (int half = 0; half < 2; half++) {
            int row = m0 + wy * 64 + mt * 16 + g + half * 8;
            if (row >= NN) continue;
#pragma unroll
            for (int nt = 0; nt < 8; nt++) {
                int col = wx * 64 + nt * 8 + 2 * t4;
                float v0 = acc[mt][nt][half * 2 + 0] + bias[col];
                float v1 = acc[mt][nt][half * 2 + 1] + bias[col + 1];
                if (reluOut) { v0 = fmaxf(v0, 0.f); v1 = fmaxf(v1, 0.f); }
                if (MODE == 0) {
                    *(float2*)&g_tmp[row * H + col] = make_float2(v0, v1);
                } else {
                    float2 rh = *(const float2*)&g_h[row * H + col];
                    *(float2*)&g_h[row * H + col] = make_float2(v0 + rh.x, v1 + rh.y);
                }
            }
        }
}

// ---------------- out1: K=512, 128x256 tile, pipelined ----------------------
#define OUT1_SMEM ((2 * ASZ + 2 * BSZ + 256) * 4)
__global__ void __launch_bounds__(256, 1)
out1(const int* __restrict__ src, const int* __restrict__ dst,
     const float* __restrict__ W1, const float* __restrict__ b1) {
    extern __shared__ float sm[];
    float* As = sm;
    float* Bs = sm + 2 * ASZ;
    int* srcS = (int*)(Bs + 2 * BSZ);   // 128
    int* dstS = srcS + 128;             // 128
    int tid = threadIdx.x, lane = tid & 31, warp = tid >> 5;
    int wy = warp >> 2, wx = warp & 3;
    int m0 = blockIdx.x * 128;

    if (tid < 128) {
        int e = m0 + tid;
        int s = 0, d = 0;
        if (e < EN) { s = src[e]; d = dst[e]; }
        srcS[tid] = s; dstS[tid] = d;
    }
    __syncthreads();

    int r = tid & 127, kh = (tid >> 7) * 8;
    int e = m0 + r;
    bool valid = (e < EN);
    float areg[8], breg[16];

    auto loadA = [&](int k0) {
        if (k0 < 256) {
            const float* hs = &g_h[srcS[r] * H + k0 + kh];
            const float* hd = &g_h[dstS[r] * H + k0 + kh];
            float4 a0 = *(const float4*)hs, a1 = *(const float4*)(hs + 4);
            float4 c0 = *(const float4*)hd, c1 = *(const float4*)(hd + 4);
            areg[0] = a0.x * c0.x; areg[1] = a0.y * c0.y;
            areg[2] = a0.z * c0.z; areg[3] = a0.w * c0.w;
            areg[4] = a1.x * c1.x; areg[5] = a1.y * c1.y;
            areg[6] = a1.z * c1.z; areg[7] = a1.w * c1.w;
        } else if (valid) {
            const float* bp = &g_bond[(size_t)e * H + (k0 - 256) + kh];
            float4 v0 = *(const float4*)bp, v1 = *(const float4*)(bp + 4);
            areg[0] = v0.x; areg[1] = v0.y; areg[2] = v0.z; areg[3] = v0.w;
            areg[4] = v1.x; areg[5] = v1.y; areg[6] = v1.z; areg[7] = v1.w;
        } else {
#pragma unroll
            for (int i = 0; i < 8; i++) areg[i] = 0.f;
        }
    };

    loadA(0);
    load_w256(breg, W1, H, 0, tid);
    store_a8(As, kh, r, areg);
    store_w256(Bs, breg, tid);
    __syncthreads();

    float acc[4][8][4] = {};
    for (int s = 0; s < 32; s++) {
        int cur = s & 1, nxt = cur ^ 1;
        if (s < 31) { loadA((s + 1) * 16); load_w256(breg, W1, H, (s + 1) * 16, tid); }
        mma_k8w<PB>(acc, As + cur * ASZ, Bs + cur * BSZ, 0, wy, wx, lane);
        mma_k8w<PB>(acc, As + cur * ASZ, Bs + cur * BSZ, 8, wy, wx, lane);
        if (s < 31) {
            store_a8(As + nxt * ASZ, kh, r, areg);
            store_w256(Bs + nxt * BSZ, breg, tid);
            __syncthreads();
        }
    }

    int g = lane >> 2, t4 = lane & 3;
#pragma unroll
    for (int mt = 0; mt < 4; mt++)
#pragma unroll
        for (int half = 0; half < 2; half++) {
            int row = m0 + wy * 64 + mt * 16 + g + half * 8;
            if (row >= EN) continue;
#pragma unroll
            for (int nt = 0; nt < 8; nt++) {
                int col = wx * 64 + nt * 8 + 2 * t4;
                float v0 = fmaxf(acc[mt][nt][half * 2 + 0] + b1[col], 0.f);
                float v1 = fmaxf(acc[mt][nt][half * 2 + 1] + b1[col + 1], 0.f);
                *(float2*)&g_h1[(size_t)row * H + col] = make_float2(v0, v1);
            }
        }
}

// ---------------- out23 fused: 128x128 tile, pipelined (static smem) --------
#define BSZ1 (16 * PB1)
__global__ void __launch_bounds__(128, 2)
out23(const float* __restrict__ W2, const float* __restrict__ b2,
      const float* __restrict__ W3, const float* __restrict__ b3,
      float* __restrict__ out) {
    __shared__ float As[2 * ASZ], Bs[2 * BSZ1];
    __shared__ float red[128 * 8];
    __shared__ float b2S[128], w3S[128];
    int tid = threadIdx.x, lane = tid & 31, warp = tid >> 5;
    int wy = warp >> 1, wx = warp & 1;
    int m0 = blockIdx.x * 128;

    b2S[tid] = b2[tid]; w3S[tid] = W3[tid];

    int e = m0 + tid;
    bool valid = (e < EN);
    float areg[16], breg[16];
    auto loadA = [&](int k0) {
        if (valid) {
            const float* p = &g_h1[(size_t)e * H + k0];
#pragma unroll
            for (int j = 0; j < 4; j++) {
                float4 v = *(const float4*)(p + 4 * j);
                areg[4 * j] = v.x; areg[4 * j + 1] = v.y;
                areg[4 * j + 2] = v.z; areg[4 * j + 3] = v.w;
            }
        } else {
#pragma unroll
            for (int i = 0; i < 16; i++) areg[i] = 0.f;
        }
    };

    loadA(0);
    load_w128(breg, W2, 128, 0, tid);
    store_a16(As, tid, areg);
    store_w128(Bs, breg, tid);
    __syncthreads();

    float acc[4][8][4] = {};
    for (int s = 0; s < 16; s++) {
        int cur = s & 1, nxt = cur ^ 1;
        if (s < 15) { loadA((s + 1) * 16); load_w128(breg, W2, 128, (s + 1) * 16, tid); }
        mma_k8w<PB1>(acc, As + cur * ASZ, Bs + cur * BSZ1, 0, wy, wx, lane);
        mma_k8w<PB1>(acc, As + cur * ASZ, Bs + cur * BSZ1, 8, wy, wx, lane);
        if (s < 15) {
            store_a16(As + nxt * ASZ, tid, areg);
            store_w128(Bs + nxt * BSZ1, breg, tid);
            __syncthreads();
        }
    }

    int g = lane >> 2, t4 = lane & 3;
#pragma unroll
    for (int mt = 0; mt < 4; mt++)
#pragma unroll
        for (int half = 0; half < 2; half++) {
            int rl = wy * 64 + mt * 16 + g + half * 8;
            float partial = 0.f;
#pragma unroll
            for (int nt = 0; nt < 8; nt++) {
                int col = wx * 64 + nt * 8 + 2 * t4;
                float h0 = fmaxf(acc[mt][nt][half * 2 + 0] + b2S[col], 0.f);
                float h1 = fmaxf(acc[mt][nt][half * 2 + 1] + b2S[col + 1], 0.f);
                partial += h0 * w3S[col] + h1 * w3S[col + 1];
            }
            red[rl * 8 + wx * 4 + t4] = partial;
        }
    __syncthreads();

    if (valid) {
        float s = 0.f;
#pragma unroll
        for (int i = 0; i < 8; i++) s += red[tid * 8 + i];
        out[e] = (s + b3[0]) * g_einv[e];
    }
}

// ---------------- launch ----------------------------------------------------
extern "C" void kernel_launch(void* const* d_in, const int* in_sizes, int n_in,
                              void* d_out, int out_size) {
    const int*   node_type = (const int*)d_in[0];
    const int*   edge_type = (const int*)d_in[1];
    const int*   edge_index = (const int*)d_in[2];
    const int*   batch = (const int*)d_in[3];
    const float* elen = (const float*)d_in[4];
    const float* t = (const float*)d_in[5];
    const float* atom_emb = (const float*)d_in[6];
    const float* bond_emb = (const float*)d_in[7];
    const float* in_W1 = (const float*)d_in[8];
    const float* in_b1 = (const float*)d_in[9];
    const float* in_W2 = (const float*)d_in[10];
    const float* in_b2 = (const float*)d_in[11];
    const float* fourier_W = (const float*)d_in[12];
    const float* temb_W = (const float*)d_in[13];
    const float* temb_b = (const float*)d_in[14];
    const float* d1W = (const float*)d_in[15];
    const float* d1b = (const float*)d_in[16];
    const float* gin_W1 = (const float*)d_in[17];
    const float* gin_b1 = (const float*)d_in[18];
    const float* gin_W2 = (const float*)d_in[19];
    const float* gin_b2 = (const float*)d_in[20];
    const float* out_W1 = (const float*)d_in[21];
    const float* out_b1 = (const float*)d_in[22];
    const float* out_W2 = (const float*)d_in[23];
    const float* out_b2 = (const float*)d_in[24];
    const float* out_W3 = (const float*)d_in[25];
    const float* out_b3 = (const float*)d_in[26];
    const int* src = edge_index;
    const int* dst = edge_index + EN;
    float* out = (float*)d_out;

    const int EB = (EN + 127) / 128;   // 2344
    const int NB = (NN + 127) / 128;   // 391

    static int attr_done = 0;
    if (!attr_done) {
        cudaFuncSetAttribute(edge_bond, cudaFuncAttributeMaxDynamicSharedMemorySize, EB_SMEM);
        cudaFuncSetAttribute(gin_mma<0>, cudaFuncAttributeMaxDynamicSharedMemorySize, GIN_SMEM);
        cudaFuncSetAttribute(gin_mma<1>, cudaFuncAttributeMaxDynamicSharedMemorySize, GIN_SMEM);
        cudaFuncSetAttribute(out1, cudaFuncAttributeMaxDynamicSharedMemorySize, OUT1_SMEM);
        attr_done = 1;
    }

    // launch order chosen so ncu (launch index 3) profiles edge_bond
    temb_fused<<<GN, 128>>>(t, fourier_W, temb_W, temb_b, d1W, d1b);      // 0
    hist<<<(EN + 255) / 256, 256>>>(dst);                                 // 1
    scan_kernel<<<1, 1024>>>();                                           // 2
    edge_bond<<<EB, 256, EB_SMEM>>>(elen, src, batch, edge_type,          // 3
                                    in_W1, in_b1, in_W2, in_b2, bond_emb);
    place<<<(EN + 255) / 256, 256>>>(src, dst);                           // 4
    init_h<<<(NN * 64 + 255) / 256, 256>>>(node_type, atom_emb);          // 5

    for (int c = 0; c < NCONV; c++) {
        gather<<<(NN + 7) / 8, 256>>>();
        gin_mma<0><<<NB, 256, GIN_SMEM>>>(gin_W1 + c * H * H, gin_b1 + c * H, 1);
        gin_mma<1><<<NB, 256, GIN_SMEM>>>(gin_W2 + c * H * H, gin_b2 + c * H,
                                          (c < NCONV - 1) ? 1 : 0);
    }

    out1<<<EB, 256, OUT1_SMEM>>>(src, dst, out_W1, out_b1);
    out23<<<EB, 128>>>(out_W2, out_b2, out_W3, out_b3, out);
}